// round 2
// baseline (speedup 1.0000x reference)
#include <cuda_runtime.h>

#define DB 160
#define HB 160
#define WB 160
#define NB 2
#define NTOT (NB*DB*HB*WB)              // 8,192,000
#define CHUNK 8
#define WCHUNKS (WB/CHUNK)               // 20
#define NCHUNKS (NB*DB*HB*WCHUNKS)       // 1,024,000
#define TPB 256
#define NBLOCKS (NCHUNKS/TPB)            // 4000 exactly

// acc[0]=sum (1+w)*bce, acc[1]=sum p, acc[2]=sum p*t, acc[3]=sum t
__device__ double g_acc[4];          // zero-initialized at module load; reset by last block
__device__ unsigned g_count;         // ditto

// Pack a row of 9 target bits (values are 0/1) into mask bits [8..0]:
// bit (8-i) = t[i]. Then pair (t[e], t[e+1]) = (mask >> (7-e)) & 3 with t[e] as MSB.
__device__ __forceinline__ int pack_row(const int* __restrict__ target, int off, bool tailok) {
    const int4 a = *(const int4*)(target + off);
    const int4 b = *(const int4*)(target + off + 4);
    int t8 = tailok ? target[off + 8] : 0;
    return (a.x << 8) | (a.y << 7) | (a.z << 6) | (a.w << 5)
         | (b.x << 4) | (b.y << 3) | (b.z << 2) | (b.w << 1) | t8;
}

__global__ __launch_bounds__(TPB) void loss_fused_kernel(
    const float* __restrict__ logits,
    const int*   __restrict__ target,
    const float* __restrict__ area_table,
    float* __restrict__ out)
{
    __shared__ float s_area[256];
    s_area[threadIdx.x] = area_table[threadIdx.x];
    __syncthreads();

    const int c  = blockIdx.x * TPB + threadIdx.x;
    const int wi = c % WCHUNKS;
    int r        = c / WCHUNKS;
    const int h  = r % HB;
    r            = r / HB;
    const int d  = r % DB;
    const int b  = r / DB;

    const int base = ((b * DB + d) * HB + h) * WB + wi * CHUNK;
    const bool tailok   = (wi < WCHUNKS - 1);
    const bool interior = (d < DB - 1) && (h < HB - 1);

    // ---- loads ----
    const float4 l0 = *(const float4*)(logits + base);
    const float4 l1 = *(const float4*)(logits + base + 4);
    float x[8] = {l0.x, l0.y, l0.z, l0.w, l1.x, l1.y, l1.z, l1.w};

    const int m00 = pack_row(target, base, tailok);
    int m01 = 0, m10 = 0, m11 = 0;
    if (interior) {
        m01 = pack_row(target, base + WB,          tailok);  // (d, h+1)
        m10 = pack_row(target, base + HB * WB,     tailok);  // (d+1, h)
        m11 = pack_row(target, base + HB * WB + WB, tailok); // (d+1, h+1)
    }
    // Last valid element index within this chunk for the code/weight term
    const int elast = tailok ? 8 : 7;   // w index wi*8+e must be < 159

    // ---- per-element math ----
    float acc_wbce = 0.f, acc_p = 0.f, acc_pt = 0.f, acc_t = 0.f;
    #pragma unroll
    for (int e = 0; e < 8; e++) {
        const float xv = x[e];
        const float tf = (float)((m00 >> (8 - e)) & 1);
        const float ex = __expf(-fabsf(xv));            // in (0,1]
        const float rr = __frcp_rn(1.f + ex);           // in [0.5,1)
        const float bce = fmaxf(xv, 0.f) - xv * tf - __logf(rr);
        const float p = (xv >= 0.f ? 1.f : ex) * rr;

        float wa = 0.f;
        if (interior && e < elast) {
            const int sh = 7 - e;
            const int code = (((m00 >> sh) & 3) << 6)
                           | (((m01 >> sh) & 3) << 4)
                           | (((m10 >> sh) & 3) << 2)
                           |  ((m11 >> sh) & 3);
            wa = s_area[code];
        }
        acc_wbce += (1.f + wa) * bce;
        acc_p    += p;
        acc_pt   += p * tf;
        acc_t    += tf;
    }

    // ---- block reduction ----
    #pragma unroll
    for (int off = 16; off > 0; off >>= 1) {
        acc_wbce += __shfl_xor_sync(0xffffffffu, acc_wbce, off);
        acc_p    += __shfl_xor_sync(0xffffffffu, acc_p,    off);
        acc_pt   += __shfl_xor_sync(0xffffffffu, acc_pt,   off);
        acc_t    += __shfl_xor_sync(0xffffffffu, acc_t,    off);
    }

    __shared__ float s_red[4][TPB / 32];
    const int lane = threadIdx.x & 31;
    const int warp = threadIdx.x >> 5;
    if (lane == 0) {
        s_red[0][warp] = acc_wbce;
        s_red[1][warp] = acc_p;
        s_red[2][warp] = acc_pt;
        s_red[3][warp] = acc_t;
    }
    __syncthreads();
    if (warp == 0) {
        const int nw = TPB / 32;
        float v0 = (lane < nw) ? s_red[0][lane] : 0.f;
        float v1 = (lane < nw) ? s_red[1][lane] : 0.f;
        float v2 = (lane < nw) ? s_red[2][lane] : 0.f;
        float v3 = (lane < nw) ? s_red[3][lane] : 0.f;
        #pragma unroll
        for (int off = 4; off > 0; off >>= 1) {
            v0 += __shfl_xor_sync(0xffffffffu, v0, off);
            v1 += __shfl_xor_sync(0xffffffffu, v1, off);
            v2 += __shfl_xor_sync(0xffffffffu, v2, off);
            v3 += __shfl_xor_sync(0xffffffffu, v3, off);
        }
        if (lane == 0) {
            atomicAdd(&g_acc[0], (double)v0);
            atomicAdd(&g_acc[1], (double)v1);
            atomicAdd(&g_acc[2], (double)v2);
            atomicAdd(&g_acc[3], (double)v3);
            __threadfence();
            const unsigned old = atomicAdd(&g_count, 1u);
            if (old == NBLOCKS - 1) {
                // Last block: all other blocks' accumulator atomics are globally
                // visible (they fenced before incrementing the counter).
                const double a0 = atomicAdd(&g_acc[0], 0.0);
                const double a1 = atomicAdd(&g_acc[1], 0.0);
                const double a2 = atomicAdd(&g_acc[2], 0.0);
                const double a3 = atomicAdd(&g_acc[3], 0.0);
                const double wbce = a0 / (double)NTOT;
                const double dice = 1.0 - (2.0 * a2 + 1.0) / (a1 + a3 + 1.0);
                out[0] = (float)(wbce + dice);
                // Reset for the next (graph-replayed) invocation.
                g_acc[0] = 0.0; g_acc[1] = 0.0; g_acc[2] = 0.0; g_acc[3] = 0.0;
                g_count = 0u;
                __threadfence();
            }
        }
    }
}

extern "C" void kernel_launch(void* const* d_in, const int* in_sizes, int n_in,
                              void* d_out, int out_size) {
    const float* logits     = (const float*)d_in[0];
    const int*   target     = (const int*)d_in[1];
    const float* area_table = (const float*)d_in[2];
    float* out = (float*)d_out;

    loss_fused_kernel<<<NBLOCKS, TPB>>>(logits, target, area_table, out);
}

// round 3
// speedup vs baseline: 1.1250x; 1.1250x over previous
#include <cuda_runtime.h>

#define DB 160
#define HB 160
#define WB 160
#define NB 2
#define NTOT (NB*DB*HB*WB)              // 8,192,000
#define PW (WB/32)                       // 5 packed words per row
#define NROWS (NB*DB*HB)                 // 51,200 rows
#define NWORDS (NROWS*PW)                // 256,000 words
#define TPB 256
#define PACK_BLOCKS (NWORDS/TPB)         // 1000
#define MAIN_BLOCKS (NWORDS/TPB)         // 1000 (one thread per word)

// acc[0]=sum (1+w)*bce, acc[1]=sum p, acc[2]=sum p*t, acc[3]=sum t
__device__ double g_acc[4];
__device__ unsigned g_packed[NWORDS];    // 1 MB bitmask scratch

// ---------------- pack: target int32 -> bitmask (32 elts/thread) --------------
__global__ __launch_bounds__(TPB) void pack_kernel(const int* __restrict__ target) {
    if (blockIdx.x == 0 && threadIdx.x < 4) g_acc[threadIdx.x] = 0.0;
    const int widx = blockIdx.x * TPB + threadIdx.x;          // < NWORDS
    const int4* tp = (const int4*)(target + (size_t)widx * 32);
    unsigned w = 0u;
    #pragma unroll
    for (int i = 0; i < 8; i++) {
        const int4 v = tp[i];
        const unsigned nib = (unsigned)(v.x | (v.y << 1) | (v.z << 2) | (v.w << 3));
        w |= nib << (4 * i);
    }
    g_packed[widx] = w;
}

// ---------------- main: fused loss over 32 elts/thread ------------------------
__global__ __launch_bounds__(TPB) void loss_main_kernel(
    const float* __restrict__ logits,
    const float* __restrict__ area_table)
{
    // Permuted table: our code' has bits LSB-first (b0=t00[e], b1=t00[e+1], ...,
    // b7=t11[e+1]); reference code is the 8-bit reverse of that.
    __shared__ float s_area2[256];
    s_area2[threadIdx.x] = area_table[__brev((unsigned)threadIdx.x) >> 24];
    __syncthreads();

    const int t  = blockIdx.x * TPB + threadIdx.x;            // word id
    const int wi = t % PW;
    int r        = t / PW;
    const int h  = r % HB;
    r            = r / HB;
    const int d  = r % DB;
    const int b  = r / DB;

    const int rwb  = t;                                        // row-major word index
    const int base = ((b * DB + d) * HB + h) * WB + wi * 32;   // element base

    const bool interior = (d < DB - 1) && (h < HB - 1);
    const bool hiok     = (wi < PW - 1);

    const unsigned m00lo = g_packed[rwb];
    const unsigned m00hi = hiok ? g_packed[rwb + 1] : 0u;
    unsigned m01lo = 0u, m01hi = 0u, m10lo = 0u, m10hi = 0u, m11lo = 0u, m11hi = 0u;
    if (interior) {
        m01lo = g_packed[rwb + PW];
        m10lo = g_packed[rwb + HB * PW];
        m11lo = g_packed[rwb + HB * PW + PW];
        if (hiok) {
            m01hi = g_packed[rwb + PW + 1];
            m10hi = g_packed[rwb + HB * PW + 1];
            m11hi = g_packed[rwb + HB * PW + PW + 1];
        }
    }
    // weight valid for element e iff e < elim (w=159 and boundary planes get 0)
    const int elim = interior ? (hiok ? 32 : 31) : 0;

    float acc_wbce = 0.f, acc_p = 0.f, acc_pt = 0.f;
    const float acc_t = (float)__popc(m00lo);

    #pragma unroll 1
    for (int q = 0; q < 4; q++) {
        const float4 l0 = *(const float4*)(logits + base + q * 8);
        const float4 l1 = *(const float4*)(logits + base + q * 8 + 4);
        const float xs[8] = {l0.x, l0.y, l0.z, l0.w, l1.x, l1.y, l1.z, l1.w};
        #pragma unroll
        for (int e2 = 0; e2 < 8; e2++) {
            const int e = q * 8 + e2;
            const float xv = xs[e2];
            const unsigned p00 = __funnelshift_r(m00lo, m00hi, e) & 3u;
            const bool bit = (p00 & 1u) != 0u;

            const float ex  = __expf(-fabsf(xv));       // (0,1]
            const float rr  = __frcp_rn(1.f + ex);      // [0.5,1)
            const float l1p = -__logf(rr);
            const float bce = fmaxf(xv, 0.f) - (bit ? xv : 0.f) + l1p;
            const float p   = (xv >= 0.f ? 1.f : ex) * rr;

            float wa = 0.f;
            if (e < elim) {
                const unsigned p01 = __funnelshift_r(m01lo, m01hi, e) & 3u;
                const unsigned p10 = __funnelshift_r(m10lo, m10hi, e) & 3u;
                const unsigned p11 = __funnelshift_r(m11lo, m11hi, e) & 3u;
                const unsigned code = p00 | (p01 << 2) | (p10 << 4) | (p11 << 6);
                wa = s_area2[code];
            }
            acc_wbce += bce;
            acc_wbce = fmaf(wa, bce, acc_wbce);
            acc_p += p;
            if (bit) acc_pt += p;
        }
    }

    // ---- block reduction ----
    float v0 = acc_wbce, v1 = acc_p, v2 = acc_pt, v3 = acc_t;
    #pragma unroll
    for (int off = 16; off > 0; off >>= 1) {
        v0 += __shfl_xor_sync(0xffffffffu, v0, off);
        v1 += __shfl_xor_sync(0xffffffffu, v1, off);
        v2 += __shfl_xor_sync(0xffffffffu, v2, off);
        v3 += __shfl_xor_sync(0xffffffffu, v3, off);
    }
    __shared__ float s_red[4][TPB / 32];
    const int lane = threadIdx.x & 31;
    const int warp = threadIdx.x >> 5;
    if (lane == 0) { s_red[0][warp] = v0; s_red[1][warp] = v1; s_red[2][warp] = v2; s_red[3][warp] = v3; }
    __syncthreads();
    if (warp == 0) {
        const int nw = TPB / 32;
        v0 = (lane < nw) ? s_red[0][lane] : 0.f;
        v1 = (lane < nw) ? s_red[1][lane] : 0.f;
        v2 = (lane < nw) ? s_red[2][lane] : 0.f;
        v3 = (lane < nw) ? s_red[3][lane] : 0.f;
        #pragma unroll
        for (int off = 4; off > 0; off >>= 1) {
            v0 += __shfl_xor_sync(0xffffffffu, v0, off);
            v1 += __shfl_xor_sync(0xffffffffu, v1, off);
            v2 += __shfl_xor_sync(0xffffffffu, v2, off);
            v3 += __shfl_xor_sync(0xffffffffu, v3, off);
        }
        if (lane == 0) {
            atomicAdd(&g_acc[0], (double)v0);
            atomicAdd(&g_acc[1], (double)v1);
            atomicAdd(&g_acc[2], (double)v2);
            atomicAdd(&g_acc[3], (double)v3);
        }
    }
}

__global__ void finalize_kernel(float* __restrict__ out) {
    const double wbce = g_acc[0] / (double)NTOT;
    const double dice = 1.0 - (2.0 * g_acc[2] + 1.0) / (g_acc[1] + g_acc[3] + 1.0);
    out[0] = (float)(wbce + dice);
}

extern "C" void kernel_launch(void* const* d_in, const int* in_sizes, int n_in,
                              void* d_out, int out_size) {
    const float* logits     = (const float*)d_in[0];
    const int*   target     = (const int*)d_in[1];
    const float* area_table = (const float*)d_in[2];
    float* out = (float*)d_out;

    pack_kernel<<<PACK_BLOCKS, TPB>>>(target);
    loss_main_kernel<<<MAIN_BLOCKS, TPB>>>(logits, area_table);
    finalize_kernel<<<1, 1>>>(out);
}

// round 4
// speedup vs baseline: 1.2843x; 1.1416x over previous
#include <cuda_runtime.h>

#define DB 160
#define HB 160
#define WB 160
#define NB 2
#define NTOT (NB*DB*HB*WB)              // 8,192,000
#define PW (WB/32)                       // 5 packed words per row
#define NWORDS (NTOT/32)                 // 256,000 words
#define TPB 256
#define PACK_EPT 4                       // elements per thread in pack
#define PACK_BLOCKS (NTOT/(TPB*PACK_EPT))// 8000
#define MAIN_BLOCKS (NWORDS/TPB)         // 1000

// acc[0]=sum (1+w)*bce, acc[1]=sum p, acc[2]=sum p*t, acc[3]=sum t
__device__ double g_acc[4];
__device__ unsigned g_count;
__device__ unsigned g_packed[NWORDS];

// ---------------- pack via warp ballot: 1 bit/elt, 1 inst/32 elts -------------
__global__ __launch_bounds__(TPB) void pack_kernel(const int* __restrict__ target) {
    if (blockIdx.x == 0 && threadIdx.x < 4) g_acc[threadIdx.x] = 0.0;
    const int tid  = blockIdx.x * TPB + threadIdx.x;
    const int lane = threadIdx.x & 31;
    const int gw   = tid >> 5;                      // global warp id
    const int ebase = gw * 32 * PACK_EPT;           // warp covers 128 consecutive elts
    unsigned keep = 0u;
    #pragma unroll
    for (int i = 0; i < PACK_EPT; i++) {
        const int v = target[ebase + i * 32 + lane];
        const unsigned w = __ballot_sync(0xffffffffu, v != 0);
        if (lane == i) keep = w;
    }
    if (lane < PACK_EPT) g_packed[gw * PACK_EPT + lane] = keep;
}

// ---------------- main: fused loss, 32 elts/thread, finalize in last block ----
__global__ __launch_bounds__(TPB) void loss_main_kernel(
    const float* __restrict__ logits,
    const float* __restrict__ area_table,
    float* __restrict__ out)
{
    // Bit-reversed copy: our code has b0=t00[e] .. b7=t11[e+1] (LSB-first);
    // reference code is the 8-bit reversal.
    __shared__ float s_area2[256];
    s_area2[threadIdx.x] = area_table[__brev((unsigned)threadIdx.x) >> 24];
    __syncthreads();

    const int t  = blockIdx.x * TPB + threadIdx.x;            // word id
    const int wi = t % PW;
    int r        = t / PW;
    const int h  = r % HB;
    r            = r / HB;
    const int d  = r % DB;

    const int base = t * 32;                                   // element base (row-major)
    const bool interior = (d < DB - 1) && (h < HB - 1);
    const bool hiok     = (wi < PW - 1);

    const unsigned m00lo = g_packed[t];
    const unsigned m00hi = hiok ? g_packed[t + 1] : 0u;
    unsigned a01lo = 0u, a01hi = 0u, a10lo = 0u, a10hi = 0u, a11lo = 0u, a11hi = 0u;
    if (interior) {
        const unsigned b01lo = g_packed[t + PW];
        const unsigned b10lo = g_packed[t + HB * PW];
        const unsigned b11lo = g_packed[t + HB * PW + PW];
        unsigned b01hi = 0u, b10hi = 0u, b11hi = 0u;
        if (hiok) {
            b01hi = g_packed[t + PW + 1];
            b10hi = g_packed[t + HB * PW + 1];
            b11hi = g_packed[t + HB * PW + PW + 1];
        }
        // Pre-shift left so per-element extraction needs no post-shift:
        a01lo = b01lo << 2; a01hi = (b01hi << 2) | (b01lo >> 30);
        a10lo = b10lo << 4; a10hi = (b10hi << 4) | (b10lo >> 28);
        a11lo = b11lo << 6; a11hi = (b11hi << 6) | (b11lo >> 26);
    }
    const int elim = interior ? (hiok ? 32 : 31) : 0;

    float acc_wbce = 0.f, acc_p = 0.f, acc_pt = 0.f;
    const float acc_t = (float)__popc(m00lo);

    #pragma unroll 1
    for (int q = 0; q < 4; q++) {
        const float4 l0 = *(const float4*)(logits + base + q * 8);
        const float4 l1 = *(const float4*)(logits + base + q * 8 + 4);
        const float xs[8] = {l0.x, l0.y, l0.z, l0.w, l1.x, l1.y, l1.z, l1.w};
        #pragma unroll
        for (int e2 = 0; e2 < 8; e2++) {
            const int e = q * 8 + e2;
            const float xv = xs[e2];
            const unsigned c00 = __funnelshift_r(m00lo, m00hi, e);
            const bool bit = (c00 & 1u) != 0u;

            // p = sigmoid(x); exp overflow saturates to the right answer.
            const float p  = __frcp_rn(1.f + __expf(-xv));
            const float mx = fmaxf(p, 1.f - p);         // = sigmoid(|x|)
            const float l1p = -__logf(mx);              // = log1p(exp(-|x|))
            const float bce = fmaxf(xv, 0.f) - (bit ? xv : 0.f) + l1p;

            float wa = 0.f;
            if (e < elim) {
                const unsigned code = (c00 & 3u)
                    | (__funnelshift_r(a01lo, a01hi, e) & 12u)
                    | (__funnelshift_r(a10lo, a10hi, e) & 48u)
                    | (__funnelshift_r(a11lo, a11hi, e) & 192u);
                wa = s_area2[code];
            }
            acc_wbce += bce;
            acc_wbce = fmaf(wa, bce, acc_wbce);
            acc_p += p;
            if (bit) acc_pt += p;
        }
    }

    // ---- block reduction ----
    float v0 = acc_wbce, v1 = acc_p, v2 = acc_pt, v3 = acc_t;
    #pragma unroll
    for (int off = 16; off > 0; off >>= 1) {
        v0 += __shfl_xor_sync(0xffffffffu, v0, off);
        v1 += __shfl_xor_sync(0xffffffffu, v1, off);
        v2 += __shfl_xor_sync(0xffffffffu, v2, off);
        v3 += __shfl_xor_sync(0xffffffffu, v3, off);
    }
    __shared__ float s_red[4][TPB / 32];
    const int lane = threadIdx.x & 31;
    const int warp = threadIdx.x >> 5;
    if (lane == 0) { s_red[0][warp] = v0; s_red[1][warp] = v1; s_red[2][warp] = v2; s_red[3][warp] = v3; }
    __syncthreads();
    if (warp == 0) {
        const int nw = TPB / 32;
        v0 = (lane < nw) ? s_red[0][lane] : 0.f;
        v1 = (lane < nw) ? s_red[1][lane] : 0.f;
        v2 = (lane < nw) ? s_red[2][lane] : 0.f;
        v3 = (lane < nw) ? s_red[3][lane] : 0.f;
        #pragma unroll
        for (int off = 4; off > 0; off >>= 1) {
            v0 += __shfl_xor_sync(0xffffffffu, v0, off);
            v1 += __shfl_xor_sync(0xffffffffu, v1, off);
            v2 += __shfl_xor_sync(0xffffffffu, v2, off);
            v3 += __shfl_xor_sync(0xffffffffu, v3, off);
        }
        if (lane == 0) {
            atomicAdd(&g_acc[0], (double)v0);
            atomicAdd(&g_acc[1], (double)v1);
            atomicAdd(&g_acc[2], (double)v2);
            atomicAdd(&g_acc[3], (double)v3);
            __threadfence();
            const unsigned old = atomicAdd(&g_count, 1u);
            if (old == MAIN_BLOCKS - 1) {
                const double a0 = atomicAdd(&g_acc[0], 0.0);
                const double a1 = atomicAdd(&g_acc[1], 0.0);
                const double a2 = atomicAdd(&g_acc[2], 0.0);
                const double a3 = atomicAdd(&g_acc[3], 0.0);
                const double wbce = a0 / (double)NTOT;
                const double dice = 1.0 - (2.0 * a2 + 1.0) / (a1 + a3 + 1.0);
                out[0] = (float)(wbce + dice);
                g_count = 0u;      // g_acc re-zeroed by next pack launch
                __threadfence();
            }
        }
    }
}

extern "C" void kernel_launch(void* const* d_in, const int* in_sizes, int n_in,
                              void* d_out, int out_size) {
    const float* logits     = (const float*)d_in[0];
    const int*   target     = (const int*)d_in[1];
    const float* area_table = (const float*)d_in[2];
    float* out = (float*)d_out;

    pack_kernel<<<PACK_BLOCKS, TPB>>>(target);
    loss_main_kernel<<<MAIN_BLOCKS, TPB>>>(logits, area_table, out);
}